// round 8
// baseline (speedup 1.0000x reference)
#include <cuda_runtime.h>
#include <stdint.h>

// Problem shape (fixed by the reference): B=32, C=3, H=W=1024, patch 256x256.
#define Bn 32
#define Cn 3
#define Hn 1024
#define Wn 1024
#define PH 256
#define PW 256

// total float elements = 32*3*1024*1024 = 100,663,296 (< 2^31, int math is safe)
#define TOTAL (Bn * Cn * Hn * Wn)
#define TOTAL4 (TOTAL / 4)

__global__ __launch_bounds__(256) void paste_kernel(
    const float* __restrict__ bg,
    const float* __restrict__ patch,
    const int* __restrict__ xs,      // JAX x64 disabled: int64 in source == int32 on device
    const int* __restrict__ ys,
    const float* __restrict__ mask,
    float* __restrict__ out)
{
    const unsigned int stride = gridDim.x * blockDim.x;
    for (unsigned int i4 = blockIdx.x * blockDim.x + threadIdx.x;
         i4 < TOTAL4; i4 += stride)
    {
        unsigned int base = i4 * 4u;           // element index, 16B aligned

        // decompose: base = ((b*C + c)*H + hh)*W + ww
        unsigned int ww = base & (Wn - 1);     // W = 1024 (pow2)
        unsigned int t  = base >> 10;          // /W
        unsigned int hh = t & (Hn - 1);        // H = 1024 (pow2)
        t >>= 10;                              // = b*C + c
        unsigned int b  = t / Cn;

        float4 v = *reinterpret_cast<const float4*>(bg + base);

        int x = __ldg(&xs[b]);
        int y = __ldg(&ys[b]);
        int dy = (int)hh - y;
        if (dy >= 0 && dy < PH) {
            int dx0 = (int)ww - x;
            if (dx0 + 3 >= 0 && dx0 < PW) {
                // patch/mask index base for this (b,c,dy) row
                unsigned int pbase = (t * PH + (unsigned)dy) * PW;  // t = b*C + c
                float* pv = &v.x;
                #pragma unroll
                for (int k = 0; k < 4; k++) {
                    int dx = dx0 + k;
                    if (dx >= 0 && dx < PW) {
                        float m = __ldg(&mask[pbase + dx]);
                        float p = __ldg(&patch[pbase + dx]);
                        pv[k] = fmaf(m, p - pv[k], pv[k]);  // m*p + (1-m)*old
                    }
                }
            }
        }

        *reinterpret_cast<float4*>(out + base) = v;
    }
}

extern "C" void kernel_launch(void* const* d_in, const int* in_sizes, int n_in,
                              void* d_out, int out_size)
{
    // metadata order: background, patch, x, y, mask
    const float* bg    = (const float*)d_in[0];
    const float* patch = (const float*)d_in[1];
    const int*   xs    = (const int*)d_in[2];
    const int*   ys    = (const int*)d_in[3];
    const float* mask  = (const float*)d_in[4];
    float*       out   = (float*)d_out;

    const int threads = 256;
    // 148 SMs x 16 blocks/SM; grid-stride keeps tail balanced & wave structure
    // deterministic.
    const int blocks = 148 * 16;
    paste_kernel<<<blocks, threads>>>(bg, patch, xs, ys, mask, out);
}

// round 11
// speedup vs baseline: 1.0031x; 1.0031x over previous
#include <cuda_runtime.h>
#include <stdint.h>

// Problem shape (fixed by the reference): B=32, C=3, H=W=1024, patch 256x256.
#define Bn 32
#define Cn 3
#define Hn 1024
#define Wn 1024
#define PH 256
#define PW 256

#define TOTAL  (Bn * Cn * Hn * Wn)   // 100,663,296 floats
#define TOTAL4 (TOTAL / 4)           // 25,165,824 float4s = 2^23 * 3

#define NBLOCKS 2048
#define NTHREADS 256
// total threads = 2^19; TOTAL4 / 2^19 = 48 float4 per thread, exact.
#define PER_THREAD 48
#define UNROLL 4
#define NITER (PER_THREAD / UNROLL)  // 12

__device__ __forceinline__ void blend4(float4& v, unsigned int base,
                                       const int* __restrict__ xs,
                                       const int* __restrict__ ys,
                                       const float* __restrict__ patch,
                                       const float* __restrict__ mask)
{
    // decompose: base = ((b*C + c)*H + hh)*W + ww
    unsigned int ww = base & (Wn - 1);
    unsigned int t  = base >> 10;
    unsigned int hh = t & (Hn - 1);
    t >>= 10;                         // b*C + c
    unsigned int b = t / Cn;

    int x = __ldg(&xs[b]);
    int y = __ldg(&ys[b]);
    int dy = (int)hh - y;
    if (dy >= 0 && dy < PH) {
        int dx0 = (int)ww - x;
        if (dx0 + 3 >= 0 && dx0 < PW) {
            unsigned int pbase = (t * PH + (unsigned)dy) * PW;
            float* pv = &v.x;
            #pragma unroll
            for (int k = 0; k < 4; k++) {
                int dx = dx0 + k;
                if (dx >= 0 && dx < PW) {
                    float m = __ldg(&mask[pbase + dx]);
                    float p = __ldg(&patch[pbase + dx]);
                    pv[k] = fmaf(m, p - pv[k], pv[k]);  // m*p + (1-m)*old
                }
            }
        }
    }
}

__global__ __launch_bounds__(NTHREADS) void paste_kernel(
    const float* __restrict__ bg,
    const float* __restrict__ patch,
    const int* __restrict__ xs,      // JAX x64 disabled: these buffers are int32
    const int* __restrict__ ys,
    const float* __restrict__ mask,
    float* __restrict__ out)
{
    const unsigned int stride = NBLOCKS * NTHREADS;            // 2^19
    unsigned int i4 = blockIdx.x * NTHREADS + threadIdx.x;

    #pragma unroll 1
    for (int it = 0; it < NITER; it++) {
        unsigned int idx[UNROLL];
        float4 v[UNROLL];
        // front-batched independent loads -> MLP 4 per warp-iteration
        #pragma unroll
        for (int u = 0; u < UNROLL; u++) {
            idx[u] = (i4 + u * stride) * 4u;
            v[u] = __ldcs(reinterpret_cast<const float4*>(bg + idx[u]));
        }
        #pragma unroll
        for (int u = 0; u < UNROLL; u++)
            blend4(v[u], idx[u], xs, ys, patch, mask);
        #pragma unroll
        for (int u = 0; u < UNROLL; u++)
            __stcs(reinterpret_cast<float4*>(out + idx[u]), v[u]);

        i4 += UNROLL * stride;
    }
}

extern "C" void kernel_launch(void* const* d_in, const int* in_sizes, int n_in,
                              void* d_out, int out_size)
{
    // metadata order: background, patch, x, y, mask
    const float* bg    = (const float*)d_in[0];
    const float* patch = (const float*)d_in[1];
    const int*   xs    = (const int*)d_in[2];
    const int*   ys    = (const int*)d_in[3];
    const float* mask  = (const float*)d_in[4];
    float*       out   = (float*)d_out;

    paste_kernel<<<NBLOCKS, NTHREADS>>>(bg, patch, xs, ys, mask, out);
}

// round 13
// speedup vs baseline: 1.0316x; 1.0284x over previous
#include <cuda_runtime.h>
#include <stdint.h>

// Problem shape (fixed by the reference): B=32, C=3, H=W=1024, patch 256x256.
#define Bn 32
#define Cn 3
#define Hn 1024
#define Wn 1024
#define PH 256
#define PW 256

#define TOTAL  (Bn * Cn * Hn * Wn)   // 100,663,296 floats
#define TOTAL4 (TOTAL / 4)           // 25,165,824 float4s

#define NBLOCKS (148 * 16)           // 2368: perfectly balanced persistent grid
#define NTHREADS 256
#define UNROLL 4

__device__ __forceinline__ void blend4(float4& v, unsigned int base,
                                       const int* __restrict__ xs,
                                       const int* __restrict__ ys,
                                       const float* __restrict__ patch,
                                       const float* __restrict__ mask)
{
    // decompose: base = ((b*C + c)*H + hh)*W + ww
    unsigned int ww = base & (Wn - 1);
    unsigned int t  = base >> 10;
    unsigned int hh = t & (Hn - 1);
    t >>= 10;                         // b*C + c
    unsigned int b = t / Cn;

    int x = __ldg(&xs[b]);
    int y = __ldg(&ys[b]);
    int dy = (int)hh - y;
    if (dy >= 0 && dy < PH) {
        int dx0 = (int)ww - x;
        if (dx0 + 3 >= 0 && dx0 < PW) {
            unsigned int pbase = (t * PH + (unsigned)dy) * PW;
            float* pv = &v.x;
            #pragma unroll
            for (int k = 0; k < 4; k++) {
                int dx = dx0 + k;
                if (dx >= 0 && dx < PW) {
                    float m = __ldg(&mask[pbase + dx]);
                    float p = __ldg(&patch[pbase + dx]);
                    pv[k] = fmaf(m, p - pv[k], pv[k]);  // m*p + (1-m)*old
                }
            }
        }
    }
}

__global__ __launch_bounds__(NTHREADS) void paste_kernel(
    const float* __restrict__ bg,
    const float* __restrict__ patch,
    const int* __restrict__ xs,      // JAX x64 disabled: these buffers are int32
    const int* __restrict__ ys,
    const float* __restrict__ mask,
    float* __restrict__ out)
{
    const unsigned int stride = NBLOCKS * NTHREADS;   // 606,208
    unsigned int i4 = blockIdx.x * NTHREADS + threadIdx.x;

    // Batched main loop: 4 independent front-batched float4 loads per trip.
    #pragma unroll 1
    while (i4 + (UNROLL - 1) * stride < TOTAL4) {
        unsigned int idx[UNROLL];
        float4 v[UNROLL];
        #pragma unroll
        for (int u = 0; u < UNROLL; u++) {
            idx[u] = (i4 + u * stride) * 4u;
            v[u] = *reinterpret_cast<const float4*>(bg + idx[u]);
        }
        #pragma unroll
        for (int u = 0; u < UNROLL; u++)
            blend4(v[u], idx[u], xs, ys, patch, mask);
        #pragma unroll
        for (int u = 0; u < UNROLL; u++)
            *reinterpret_cast<float4*>(out + idx[u]) = v[u];
        i4 += UNROLL * stride;
    }

    // Tail: remaining strides (TOTAL4/stride = 41.5, so up to 2 single trips).
    #pragma unroll 1
    for (; i4 < TOTAL4; i4 += stride) {
        unsigned int base = i4 * 4u;
        float4 v = *reinterpret_cast<const float4*>(bg + base);
        blend4(v, base, xs, ys, patch, mask);
        *reinterpret_cast<float4*>(out + base) = v;
    }
}

extern "C" void kernel_launch(void* const* d_in, const int* in_sizes, int n_in,
                              void* d_out, int out_size)
{
    // metadata order: background, patch, x, y, mask
    const float* bg    = (const float*)d_in[0];
    const float* patch = (const float*)d_in[1];
    const int*   xs    = (const int*)d_in[2];
    const int*   ys    = (const int*)d_in[3];
    const float* mask  = (const float*)d_in[4];
    float*       out   = (float*)d_out;

    paste_kernel<<<NBLOCKS, NTHREADS>>>(bg, patch, xs, ys, mask, out);
}